// round 8
// baseline (speedup 1.0000x reference)
#include <cuda_runtime.h>
#include <cstdint>

#define IN_DIM   5000
#define TOPK     50
#define BATCH    16384
#define H1       32
#define H2       16
#define OUT_DIM  30

#define NBIN     4096
#define MAXCAND  512

#define RW        4                         // rows per warp (pipelined)
#define MLP_BLK   128                       // 4 warps
#define MLP_GRID  (BATCH / (4 * RW))        // 1024

// scratch (no allocations allowed)
__device__ int g_topk_idx[64];

static __device__ __forceinline__ unsigned key32(float f) {
    unsigned u = __float_as_uint(f);
    return (u & 0x80000000u) ? ~u : (u | 0x80000000u);  // monotonic
}

// ---------------------------------------------------------------------------
// Kernel 1: single-CTA histogram top-k -> mask + compact index list
// ---------------------------------------------------------------------------
__global__ void __launch_bounds__(1024, 1)
k_topk(const float* __restrict__ logits, float* __restrict__ mask_out) {
    __shared__ unsigned skey[IN_DIM];
    __shared__ int hist[NBIN];
    __shared__ int groupsum[128];
    __shared__ int sgrp[128];
    __shared__ int sbin[32];
    __shared__ int s_g, s_above, s_T, s_m, s_ncand;
    __shared__ int      cand_idx[MAXCAND];
    __shared__ unsigned cand_key[MAXCAND];
    __shared__ unsigned char sel[IN_DIM];
    __shared__ int wcnt[32], wbase[32];

    const int tid = threadIdx.x;
    const int w = tid >> 5, l = tid & 31;

    for (int i = tid; i < NBIN; i += 1024) hist[i] = 0;
    if (tid == 0) s_ncand = 0;
    __syncthreads();

    for (int i = tid; i < IN_DIM; i += 1024) {
        unsigned u = key32(logits[i]);
        skey[i] = u;
        atomicAdd(&hist[u >> 20], 1);
    }
    __syncthreads();

    if (tid < 128) {
        int s = 0;
#pragma unroll
        for (int j = 0; j < 32; j++) s += hist[tid * 32 + j];
        groupsum[tid] = s;
    }
    __syncthreads();
    if (tid < 128) {
        int s = 0;
        for (int g = tid; g < 128; g++) s += groupsum[g];
        sgrp[tid] = s;
    }
    __syncthreads();
    if (tid < 128) {
        const int nxt = (tid == 127) ? 0 : sgrp[tid + 1];
        if (sgrp[tid] >= TOPK && nxt < TOPK) { s_g = tid; s_above = nxt; }
    }
    __syncthreads();
    if (tid < 32) {
        const int b0 = s_g * 32;
        int s = 0;
        for (int b = b0 + tid; b < b0 + 32; b++) s += hist[b];
        sbin[tid] = s;
    }
    __syncthreads();
    if (tid < 32) {
        const int cur = sbin[tid] + s_above;
        const int nxt = (tid == 31) ? s_above : (sbin[tid + 1] + s_above);
        if (cur >= TOPK && nxt < TOPK) { s_T = s_g * 32 + tid; s_m = TOPK - nxt; }
    }
    __syncthreads();
    const int T = s_T, m = s_m;

    for (int i = tid; i < IN_DIM; i += 1024) {
        const int b = (int)(skey[i] >> 20);
        sel[i] = (b > T) ? 1 : 0;
        if (b == T) {
            int c = atomicAdd(&s_ncand, 1);
            if (c < MAXCAND) { cand_idx[c] = i; cand_key[c] = skey[i]; }
        }
    }
    __syncthreads();

    const int nc = min(s_ncand, MAXCAND);
    for (int ci = tid; ci < nc; ci += 1024) {
        const unsigned ki = cand_key[ci];
        const int      ii = cand_idx[ci];
        int rank = 0;
        for (int cj = 0; cj < nc; cj++) {
            const unsigned kj = cand_key[cj];
            rank += (kj > ki || (kj == ki && cand_idx[cj] < ii)) ? 1 : 0;
        }
        if (rank < m) sel[ii] = 1;
    }
    __syncthreads();

    if (mask_out)
        for (int i = tid; i < IN_DIM; i += 1024)
            mask_out[i] = sel[i] ? 1.0f : 0.0f;

    // parallel index-ordered compaction
    unsigned bm[5];
    int cnt = 0;
#pragma unroll
    for (int c = 0; c < 5; c++) {
        const int i = w * 160 + c * 32 + l;
        const bool s = (i < IN_DIM) && sel[i];
        bm[c] = __ballot_sync(0xffffffffu, s);
        cnt += __popc(bm[c]);
    }
    if (l == 0) wcnt[w] = cnt;
    __syncthreads();
    if (tid < 32) {
        int v = wcnt[tid];
        int inc = v;
#pragma unroll
        for (int d = 1; d < 32; d <<= 1) {
            int t = __shfl_up_sync(0xffffffffu, inc, d);
            if (tid >= d) inc += t;
        }
        wbase[tid] = inc - v;
    }
    __syncthreads();
    int base = wbase[w];
#pragma unroll
    for (int c = 0; c < 5; c++) {
        const int i = w * 160 + c * 32 + l;
        const unsigned b = bm[c];
        if ((i < IN_DIM) && sel[i])
            g_topk_idx[base + __popc(b & ((1u << l) - 1u))] = i;
        base += __popc(b);
    }
}

// ---------------------------------------------------------------------------
// Kernel 2: sector-coalesced warp-per-row gather, PIPELINED 4 ROWS DEEP.
//   All 4 rows' 13 sector-LDGs (52 total) issue before any compute, keeping
//   ~52 lines in flight per warp continuously. __ldcg: L2-only (single-use).
//   grid = 1024, block = 128 (4 warps x 4 rows = 16 rows per CTA)
// ---------------------------------------------------------------------------
__global__ void __launch_bounds__(MLP_BLK, 5)
k_mlp(const float* __restrict__ x,
      const float* __restrict__ W1, const float* __restrict__ b1,
      const float* __restrict__ W2, const float* __restrict__ b2,
      const float* __restrict__ W3, const float* __restrict__ b3,
      float* __restrict__ out) {
    __shared__ int   ssec[52];        // sector base (col & ~7), padded
    __shared__ int   ssrc[52];        // shfl source lane: ((k&3)<<3) | (col&7)
    __shared__ float sW1[TOPK * H1];  // [k][j]
    __shared__ float sW2[H1 * H2];
    __shared__ float sW3[H2 * OUT_DIM];
    __shared__ float sb1[H1], sb2[H2], sb3[OUT_DIM];
    __shared__ int   sidx_tmp[TOPK];

    const int tid  = threadIdx.x;
    const int warp = tid >> 5;
    const int lane = tid & 31;

    if (tid < TOPK) {
        const int c = g_topk_idx[tid];
        sidx_tmp[tid] = c;
        ssec[tid] = c & ~7;
        ssrc[tid] = ((tid & 3) << 3) | (c & 7);
    }
    if (tid >= TOPK && tid < 52) { ssec[tid] = 0; ssrc[tid] = 0; }
    __syncthreads();

    for (int t = tid; t < TOPK * H1; t += MLP_BLK)
        sW1[t] = W1[(long)sidx_tmp[t >> 5] * H1 + (t & 31)];
    for (int t = tid; t < H1 * H2; t += MLP_BLK)      sW2[t] = W2[t];
    for (int t = tid; t < H2 * OUT_DIM; t += MLP_BLK) sW3[t] = W3[t];
    if (tid < H1)      sb1[tid] = b1[tid];
    if (tid < H2)      sb2[tid] = b2[tid];
    if (tid < OUT_DIM) sb3[tid] = b3[tid];
    __syncthreads();

    // lane's fixed per-row offsets: group g loads k = 4g + (lane>>3),
    // in-sector offset (lane&7)
    int myoff[13];
#pragma unroll
    for (int g = 0; g < 13; g++)
        myoff[g] = ssec[4 * g + (lane >> 3)] + (lane & 7);

    const int row0 = (blockIdx.x * 4 + warp) * RW;

    // ---- pipeline fill: issue ALL 52 gathers for 4 rows before compute ----
    float lv[RW][13];
#pragma unroll
    for (int rr = 0; rr < RW; rr++) {
        const float* __restrict__ xr = x + (long)(row0 + rr) * IN_DIM;
#pragma unroll
        for (int g = 0; g < 13; g++)
            lv[rr][g] = __ldcg(xr + myoff[g]);
    }

    // ---- compute 4 rows ----
#pragma unroll
    for (int rr = 0; rr < RW; rr++) {
        const int row = row0 + rr;

        // layer 1: lane owns output j = lane
        float p = sb1[lane];
#pragma unroll
        for (int k = 0; k < TOPK; k++) {
            const float v = __shfl_sync(0xffffffffu, lv[rr][k >> 2], ssrc[k]);
            p = fmaf(v, sW1[k * H1 + lane], p);
        }
        const float a1 = fmaxf(p, 0.0f);

        // layer 2: lane computes output (lane & 15), halves duplicate
        const int j2 = lane & 15;
        float s2 = sb2[j2];
#pragma unroll
        for (int i = 0; i < H1; i++) {
            const float v = __shfl_sync(0xffffffffu, a1, i);
            s2 = fmaf(v, sW2[i * H2 + j2], s2);
        }
        const float a2 = fmaxf(s2, 0.0f);

        // layer 3: lane j < 30 computes output j
        float o = (lane < OUT_DIM) ? sb3[lane] : 0.0f;
#pragma unroll
        for (int i = 0; i < H2; i++) {
            const float v = __shfl_sync(0xffffffffu, a2, i);
            if (lane < OUT_DIM)
                o = fmaf(v, sW3[i * OUT_DIM + lane], o);
        }
        if (lane < OUT_DIM)
            out[(long)row * OUT_DIM + lane] = o;   // 120B contiguous / warp
    }
}

// ---------------------------------------------------------------------------
extern "C" void kernel_launch(void* const* d_in, const int* in_sizes, int n_in,
                              void* d_out, int out_size) {
    const float* x      = (const float*)d_in[0];
    const float* logits = (const float*)d_in[1];
    const float* W1     = (const float*)d_in[2];
    const float* b1     = (const float*)d_in[3];
    const float* W2     = (const float*)d_in[4];
    const float* b2     = (const float*)d_in[5];
    const float* W3     = (const float*)d_in[6];
    const float* b3     = (const float*)d_in[7];

    float* out  = (float*)d_out;
    float* mask = nullptr;
    if (out_size >= BATCH * OUT_DIM + IN_DIM)
        mask = out + (long)BATCH * OUT_DIM;   // tuple order: (out, mask)

    k_topk<<<1, 1024>>>(logits, mask);
    k_mlp <<<MLP_GRID, MLP_BLK>>>(x, W1, b1, W2, b2, W3, b3, out);
}

// round 9
// speedup vs baseline: 1.1179x; 1.1179x over previous
#include <cuda_runtime.h>
#include <cstdint>

#define IN_DIM   5000
#define TOPK     50
#define BATCH    16384
#define H1       32
#define H2       16
#define OUT_DIM  30

#define NBIN     4096
#define MAXCAND  512

#define ROWS_CTA  32                     // rows per CTA
#define HALF      16                     // double-buffer half
#define MLP_BLK   256                    // 8 warps; 4 rows per warp
#define MLP_GRID  (BATCH / ROWS_CTA)     // 512

// scratch (no allocations allowed)
__device__ int g_topk_idx[64];

static __device__ __forceinline__ unsigned key32(float f) {
    unsigned u = __float_as_uint(f);
    return (u & 0x80000000u) ? ~u : (u | 0x80000000u);  // monotonic
}

// ---------------------------------------------------------------------------
// Kernel 1: single-CTA histogram top-k -> mask + compact index list
// ---------------------------------------------------------------------------
__global__ void __launch_bounds__(1024, 1)
k_topk(const float* __restrict__ logits, float* __restrict__ mask_out) {
    __shared__ unsigned skey[IN_DIM];
    __shared__ int hist[NBIN];
    __shared__ int groupsum[128];
    __shared__ int sgrp[128];
    __shared__ int sbin[32];
    __shared__ int s_g, s_above, s_T, s_m, s_ncand;
    __shared__ int      cand_idx[MAXCAND];
    __shared__ unsigned cand_key[MAXCAND];
    __shared__ unsigned char sel[IN_DIM];
    __shared__ int wcnt[32], wbase[32];

    const int tid = threadIdx.x;
    const int w = tid >> 5, l = tid & 31;

    for (int i = tid; i < NBIN; i += 1024) hist[i] = 0;
    if (tid == 0) s_ncand = 0;
    __syncthreads();

    for (int i = tid; i < IN_DIM; i += 1024) {
        unsigned u = key32(logits[i]);
        skey[i] = u;
        atomicAdd(&hist[u >> 20], 1);
    }
    __syncthreads();

    if (tid < 128) {
        int s = 0;
#pragma unroll
        for (int j = 0; j < 32; j++) s += hist[tid * 32 + j];
        groupsum[tid] = s;
    }
    __syncthreads();
    if (tid < 128) {
        int s = 0;
        for (int g = tid; g < 128; g++) s += groupsum[g];
        sgrp[tid] = s;
    }
    __syncthreads();
    if (tid < 128) {
        const int nxt = (tid == 127) ? 0 : sgrp[tid + 1];
        if (sgrp[tid] >= TOPK && nxt < TOPK) { s_g = tid; s_above = nxt; }
    }
    __syncthreads();
    if (tid < 32) {
        const int b0 = s_g * 32;
        int s = 0;
        for (int b = b0 + tid; b < b0 + 32; b++) s += hist[b];
        sbin[tid] = s;
    }
    __syncthreads();
    if (tid < 32) {
        const int cur = sbin[tid] + s_above;
        const int nxt = (tid == 31) ? s_above : (sbin[tid + 1] + s_above);
        if (cur >= TOPK && nxt < TOPK) { s_T = s_g * 32 + tid; s_m = TOPK - nxt; }
    }
    __syncthreads();
    const int T = s_T, m = s_m;

    for (int i = tid; i < IN_DIM; i += 1024) {
        const int b = (int)(skey[i] >> 20);
        sel[i] = (b > T) ? 1 : 0;
        if (b == T) {
            int c = atomicAdd(&s_ncand, 1);
            if (c < MAXCAND) { cand_idx[c] = i; cand_key[c] = skey[i]; }
        }
    }
    __syncthreads();

    const int nc = min(s_ncand, MAXCAND);
    for (int ci = tid; ci < nc; ci += 1024) {
        const unsigned ki = cand_key[ci];
        const int      ii = cand_idx[ci];
        int rank = 0;
        for (int cj = 0; cj < nc; cj++) {
            const unsigned kj = cand_key[cj];
            rank += (kj > ki || (kj == ki && cand_idx[cj] < ii)) ? 1 : 0;
        }
        if (rank < m) sel[ii] = 1;
    }
    __syncthreads();

    if (mask_out)
        for (int i = tid; i < IN_DIM; i += 1024)
            mask_out[i] = sel[i] ? 1.0f : 0.0f;

    // parallel index-ordered compaction
    unsigned bm[5];
    int cnt = 0;
#pragma unroll
    for (int c = 0; c < 5; c++) {
        const int i = w * 160 + c * 32 + l;
        const bool s = (i < IN_DIM) && sel[i];
        bm[c] = __ballot_sync(0xffffffffu, s);
        cnt += __popc(bm[c]);
    }
    if (l == 0) wcnt[w] = cnt;
    __syncthreads();
    if (tid < 32) {
        int v = wcnt[tid];
        int inc = v;
#pragma unroll
        for (int d = 1; d < 32; d <<= 1) {
            int t = __shfl_up_sync(0xffffffffu, inc, d);
            if (tid >= d) inc += t;
        }
        wbase[tid] = inc - v;
    }
    __syncthreads();
    int base = wbase[w];
#pragma unroll
    for (int c = 0; c < 5; c++) {
        const int i = w * 160 + c * 32 + l;
        const unsigned b = bm[c];
        if ((i < IN_DIM) && sel[i])
            g_topk_idx[base + __popc(b & ((1u << l) - 1u))] = i;
        base += __popc(b);
    }
}

// ---------------------------------------------------------------------------
// Kernel 2: cp.async (LDGSTS) element gather -> smem, then warp-per-row MLP.
//   1600 fire-and-forget 4B cp.asyncs per CTA (no registers, no scoreboard
//   cap), double-buffered in 2 halves; compute overlaps the 2nd half flight.
//   grid = 512, block = 256 (8 warps x 4 rows)
// ---------------------------------------------------------------------------
__global__ void __launch_bounds__(MLP_BLK, 6)
k_mlp(const float* __restrict__ x,
      const float* __restrict__ W1, const float* __restrict__ b1,
      const float* __restrict__ W2, const float* __restrict__ b2,
      const float* __restrict__ W3, const float* __restrict__ b3,
      float* __restrict__ out) {
    __shared__ float xs[ROWS_CTA][52];   // gathered inputs
    __shared__ int   sidx[TOPK];
    __shared__ float sW1[TOPK * H1];     // [k][j]
    __shared__ float sW2[H1 * H2];
    __shared__ float sW3[H2 * OUT_DIM];
    __shared__ float sb1[H1], sb2[H2], sb3[OUT_DIM];

    const int tid  = threadIdx.x;
    const int warp = tid >> 5;
    const int lane = tid & 31;
    const int row0 = blockIdx.x * ROWS_CTA;

    if (tid < TOPK) sidx[tid] = g_topk_idx[tid];
    __syncthreads();

    // ---- half A: rows [0,16) -- 800 cp.asyncs, fire-and-forget ----
    for (int e = tid; e < HALF * TOPK; e += MLP_BLK) {
        const int r = e / TOPK, k = e - r * TOPK;
        const float* src = x + (long)(row0 + r) * IN_DIM + sidx[k];
        const unsigned dst = (unsigned)__cvta_generic_to_shared(&xs[r][k]);
        asm volatile("cp.async.ca.shared.global [%0], [%1], 4;" :: "r"(dst), "l"(src));
    }
    asm volatile("cp.async.commit_group;");

    // ---- half B: rows [16,32) ----
    for (int e = tid; e < HALF * TOPK; e += MLP_BLK) {
        const int r = e / TOPK, k = e - r * TOPK;
        const float* src = x + (long)(row0 + HALF + r) * IN_DIM + sidx[k];
        const unsigned dst = (unsigned)__cvta_generic_to_shared(&xs[HALF + r][k]);
        asm volatile("cp.async.ca.shared.global [%0], [%1], 4;" :: "r"(dst), "l"(src));
    }
    asm volatile("cp.async.commit_group;");

    // ---- weight staging overlaps the cp.async flight ----
    for (int t = tid; t < TOPK * H1; t += MLP_BLK)
        sW1[t] = W1[(long)sidx[t >> 5] * H1 + (t & 31)];
    for (int t = tid; t < H1 * H2; t += MLP_BLK)      sW2[t] = W2[t];
    for (int t = tid; t < H2 * OUT_DIM; t += MLP_BLK) sW3[t] = W3[t];
    if (tid < H1)      sb1[tid] = b1[tid];
    if (tid < H2)      sb2[tid] = b2[tid];
    if (tid < OUT_DIM) sb3[tid] = b3[tid];

    // wait for half A (<=1 group outstanding), weights done via sync
    asm volatile("cp.async.wait_group 1;");
    __syncthreads();

    // warp handles 4 rows: half A -> rows warp*2, warp*2+1 ... split 2+2
#pragma unroll
    for (int half = 0; half < 2; half++) {
        if (half == 1) {
            asm volatile("cp.async.wait_group 0;");
            __syncthreads();
        }
#pragma unroll
        for (int rr = 0; rr < 2; rr++) {
            const int rloc = half * HALF + warp * 2 + rr;
            const int row  = row0 + rloc;

            // lane-resident x values: k=lane and k=32+lane (lane<18)
            const float lvA = xs[rloc][lane];
            const float lvB = xs[rloc][(lane < 18) ? (32 + lane) : 32];

            // layer 1: lane owns output j = lane
            float p = sb1[lane];
#pragma unroll
            for (int k = 0; k < 32; k++) {
                const float v = __shfl_sync(0xffffffffu, lvA, k);
                p = fmaf(v, sW1[k * H1 + lane], p);
            }
#pragma unroll
            for (int k = 32; k < TOPK; k++) {
                const float v = __shfl_sync(0xffffffffu, lvB, k - 32);
                p = fmaf(v, sW1[k * H1 + lane], p);
            }
            const float a1 = fmaxf(p, 0.0f);

            // layer 2: lane computes output (lane & 15); halves duplicate
            const int j2 = lane & 15;
            float s2 = sb2[j2];
#pragma unroll
            for (int i = 0; i < H1; i++) {
                const float v = __shfl_sync(0xffffffffu, a1, i);
                s2 = fmaf(v, sW2[i * H2 + j2], s2);
            }
            const float a2 = fmaxf(s2, 0.0f);

            // layer 3: lane j < 30 computes output j
            float o = (lane < OUT_DIM) ? sb3[lane] : 0.0f;
#pragma unroll
            for (int i = 0; i < H2; i++) {
                const float v = __shfl_sync(0xffffffffu, a2, i);
                if (lane < OUT_DIM)
                    o = fmaf(v, sW3[i * OUT_DIM + lane], o);
            }
            if (lane < OUT_DIM)
                out[(long)row * OUT_DIM + lane] = o;   // 120B / warp
        }
    }
}

// ---------------------------------------------------------------------------
extern "C" void kernel_launch(void* const* d_in, const int* in_sizes, int n_in,
                              void* d_out, int out_size) {
    const float* x      = (const float*)d_in[0];
    const float* logits = (const float*)d_in[1];
    const float* W1     = (const float*)d_in[2];
    const float* b1     = (const float*)d_in[3];
    const float* W2     = (const float*)d_in[4];
    const float* b2     = (const float*)d_in[5];
    const float* W3     = (const float*)d_in[6];
    const float* b3     = (const float*)d_in[7];

    float* out  = (float*)d_out;
    float* mask = nullptr;
    if (out_size >= BATCH * OUT_DIM + IN_DIM)
        mask = out + (long)BATCH * OUT_DIM;   // tuple order: (out, mask)

    k_topk<<<1, 1024>>>(logits, mask);
    k_mlp <<<MLP_GRID, MLP_BLK>>>(x, W1, b1, W2, b2, W3, b3, out);
}

// round 10
// speedup vs baseline: 1.7724x; 1.5854x over previous
#include <cuda_runtime.h>
#include <cstdint>

#define IN_DIM   5000
#define TOPK     50
#define BATCH    16384
#define H1       32
#define H2       16
#define OUT_DIM  30

#define NBIN     4096
#define MAXCAND  512

#define RW        2                      // rows per warp, loads prefetched
#define MLP_BLK   256                    // 8 warps -> 16 rows per CTA
#define MLP_GRID  (BATCH / (8 * RW))     // 1024 CTAs (~7 per SM)

// scratch (no allocations allowed)
__device__ int g_topk_idx[64];

static __device__ __forceinline__ unsigned key32(float f) {
    unsigned u = __float_as_uint(f);
    return (u & 0x80000000u) ? ~u : (u | 0x80000000u);  // monotonic
}

// ---------------------------------------------------------------------------
// Kernel 1: single-CTA histogram top-k -> mask + compact index list
// ---------------------------------------------------------------------------
__global__ void __launch_bounds__(1024, 1)
k_topk(const float* __restrict__ logits, float* __restrict__ mask_out) {
    __shared__ unsigned skey[IN_DIM];
    __shared__ int hist[NBIN];
    __shared__ int groupsum[128];
    __shared__ int sgrp[128];
    __shared__ int sbin[32];
    __shared__ int s_g, s_above, s_T, s_m, s_ncand;
    __shared__ int      cand_idx[MAXCAND];
    __shared__ unsigned cand_key[MAXCAND];
    __shared__ unsigned char sel[IN_DIM];
    __shared__ int wcnt[32], wbase[32];

    const int tid = threadIdx.x;
    const int w = tid >> 5, l = tid & 31;

    for (int i = tid; i < NBIN; i += 1024) hist[i] = 0;
    if (tid == 0) s_ncand = 0;
    __syncthreads();

    for (int i = tid; i < IN_DIM; i += 1024) {
        unsigned u = key32(logits[i]);
        skey[i] = u;
        atomicAdd(&hist[u >> 20], 1);
    }
    __syncthreads();

    if (tid < 128) {
        int s = 0;
#pragma unroll
        for (int j = 0; j < 32; j++) s += hist[tid * 32 + j];
        groupsum[tid] = s;
    }
    __syncthreads();
    if (tid < 128) {
        int s = 0;
        for (int g = tid; g < 128; g++) s += groupsum[g];
        sgrp[tid] = s;
    }
    __syncthreads();
    if (tid < 128) {
        const int nxt = (tid == 127) ? 0 : sgrp[tid + 1];
        if (sgrp[tid] >= TOPK && nxt < TOPK) { s_g = tid; s_above = nxt; }
    }
    __syncthreads();
    if (tid < 32) {
        const int b0 = s_g * 32;
        int s = 0;
        for (int b = b0 + tid; b < b0 + 32; b++) s += hist[b];
        sbin[tid] = s;
    }
    __syncthreads();
    if (tid < 32) {
        const int cur = sbin[tid] + s_above;
        const int nxt = (tid == 31) ? s_above : (sbin[tid + 1] + s_above);
        if (cur >= TOPK && nxt < TOPK) { s_T = s_g * 32 + tid; s_m = TOPK - nxt; }
    }
    __syncthreads();
    const int T = s_T, m = s_m;

    for (int i = tid; i < IN_DIM; i += 1024) {
        const int b = (int)(skey[i] >> 20);
        sel[i] = (b > T) ? 1 : 0;
        if (b == T) {
            int c = atomicAdd(&s_ncand, 1);
            if (c < MAXCAND) { cand_idx[c] = i; cand_key[c] = skey[i]; }
        }
    }
    __syncthreads();

    const int nc = min(s_ncand, MAXCAND);
    for (int ci = tid; ci < nc; ci += 1024) {
        const unsigned ki = cand_key[ci];
        const int      ii = cand_idx[ci];
        int rank = 0;
        for (int cj = 0; cj < nc; cj++) {
            const unsigned kj = cand_key[cj];
            rank += (kj > ki || (kj == ki && cand_idx[cj] < ii)) ? 1 : 0;
        }
        if (rank < m) sel[ii] = 1;
    }
    __syncthreads();

    if (mask_out)
        for (int i = tid; i < IN_DIM; i += 1024)
            mask_out[i] = sel[i] ? 1.0f : 0.0f;

    // parallel index-ordered compaction
    unsigned bm[5];
    int cnt = 0;
#pragma unroll
    for (int c = 0; c < 5; c++) {
        const int i = w * 160 + c * 32 + l;
        const bool s = (i < IN_DIM) && sel[i];
        bm[c] = __ballot_sync(0xffffffffu, s);
        cnt += __popc(bm[c]);
    }
    if (l == 0) wcnt[w] = cnt;
    __syncthreads();
    if (tid < 32) {
        int v = wcnt[tid];
        int inc = v;
#pragma unroll
        for (int d = 1; d < 32; d <<= 1) {
            int t = __shfl_up_sync(0xffffffffu, inc, d);
            if (tid >= d) inc += t;
        }
        wbase[tid] = inc - v;
    }
    __syncthreads();
    int base = wbase[w];
#pragma unroll
    for (int c = 0; c < 5; c++) {
        const int i = w * 160 + c * 32 + l;
        const unsigned b = bm[c];
        if ((i < IN_DIM) && sel[i])
            g_topk_idx[base + __popc(b & ((1u << l) - 1u))] = i;
        base += __popc(b);
    }
}

// ---------------------------------------------------------------------------
// Kernel 2: sector-coalesced warp-per-row gather (13 LDGs cover a row's 50
//   columns; 4 sectors per LDG) with 2 rows prefetched per warp and HIGH CTA
//   count (1024) -> ~24+ warps/SM, ~600 lines in flight per SM.
//   PDL: weights staged before cudaGridDependencySynchronize() hides k_topk.
// ---------------------------------------------------------------------------
__global__ void __launch_bounds__(MLP_BLK, 3)
k_mlp(const float* __restrict__ x,
      const float* __restrict__ W1, const float* __restrict__ b1,
      const float* __restrict__ W2, const float* __restrict__ b2,
      const float* __restrict__ W3, const float* __restrict__ b3,
      float* __restrict__ out) {
    __shared__ int   ssec[52];        // sector base (col & ~7), padded
    __shared__ int   ssrc[52];        // shfl source lane: ((k&3)<<3) | (col&7)
    __shared__ float sW1[TOPK * H1];  // [k][j]
    __shared__ float sW2[H1 * H2];
    __shared__ float sW3[H2 * OUT_DIM];
    __shared__ float sb1[H1], sb2[H2], sb3[OUT_DIM];
    __shared__ int   sidx_tmp[TOPK];

    const int tid  = threadIdx.x;
    const int warp = tid >> 5;
    const int lane = tid & 31;

    // ---- stage topk-independent weights while k_topk may still run (PDL) ----
    for (int t = tid; t < H1 * H2; t += MLP_BLK)      sW2[t] = W2[t];
    for (int t = tid; t < H2 * OUT_DIM; t += MLP_BLK) sW3[t] = W3[t];
    if (tid < H1)      sb1[tid] = b1[tid];
    if (tid < H2)      sb2[tid] = b2[tid];
    if (tid < OUT_DIM) sb3[tid] = b3[tid];

#if __CUDA_ARCH__ >= 900
    cudaGridDependencySynchronize();
#endif

    if (tid < TOPK) {
        const int c = g_topk_idx[tid];
        sidx_tmp[tid] = c;
        ssec[tid] = c & ~7;
        ssrc[tid] = ((tid & 3) << 3) | (c & 7);
    }
    if (tid >= TOPK && tid < 52) { ssec[tid] = 0; ssrc[tid] = 0; }
    __syncthreads();

    for (int t = tid; t < TOPK * H1; t += MLP_BLK)
        sW1[t] = W1[(long)sidx_tmp[t >> 5] * H1 + (t & 31)];

    // lane's fixed per-row offsets: group g loads k = 4g + (lane>>3),
    // in-sector offset (lane&7)
    int myoff[13];
#pragma unroll
    for (int g = 0; g < 13; g++)
        myoff[g] = ssec[4 * g + (lane >> 3)] + (lane & 7);

    const int row0 = (blockIdx.x * 8 + warp) * RW;

    // prefetch BOTH rows' 13 sector-gather LDGs (26 in flight per warp)
    float lv[RW][13];
#pragma unroll
    for (int rr = 0; rr < RW; rr++) {
        const float* __restrict__ xr = x + (long)(row0 + rr) * IN_DIM;
#pragma unroll
        for (int g = 0; g < 13; g++)
            lv[rr][g] = __ldg(xr + myoff[g]);
    }

    __syncthreads();   // sW1 ready

#pragma unroll
    for (int rr = 0; rr < RW; rr++) {
        const int row = row0 + rr;

        // layer 1: lane owns output j = lane
        float p = sb1[lane];
#pragma unroll
        for (int k = 0; k < TOPK; k++) {
            const float v = __shfl_sync(0xffffffffu, lv[rr][k >> 2], ssrc[k]);
            p = fmaf(v, sW1[k * H1 + lane], p);
        }
        const float a1 = fmaxf(p, 0.0f);

        // layer 2: lane computes output (lane & 15); halves duplicate
        const int j2 = lane & 15;
        float s2 = sb2[j2];
#pragma unroll
        for (int i = 0; i < H1; i++) {
            const float v = __shfl_sync(0xffffffffu, a1, i);
            s2 = fmaf(v, sW2[i * H2 + j2], s2);
        }
        const float a2 = fmaxf(s2, 0.0f);

        // layer 3: lane j < 30 computes output j
        float o = (lane < OUT_DIM) ? sb3[lane] : 0.0f;
#pragma unroll
        for (int i = 0; i < H2; i++) {
            const float v = __shfl_sync(0xffffffffu, a2, i);
            if (lane < OUT_DIM)
                o = fmaf(v, sW3[i * OUT_DIM + lane], o);
        }
        if (lane < OUT_DIM)
            out[(long)row * OUT_DIM + lane] = o;   // 120B contiguous / warp
    }
}

// ---------------------------------------------------------------------------
extern "C" void kernel_launch(void* const* d_in, const int* in_sizes, int n_in,
                              void* d_out, int out_size) {
    const float* x      = (const float*)d_in[0];
    const float* logits = (const float*)d_in[1];
    const float* W1     = (const float*)d_in[2];
    const float* b1     = (const float*)d_in[3];
    const float* W2     = (const float*)d_in[4];
    const float* b2     = (const float*)d_in[5];
    const float* W3     = (const float*)d_in[6];
    const float* b3     = (const float*)d_in[7];

    float* out  = (float*)d_out;
    float* mask = nullptr;
    if (out_size >= BATCH * OUT_DIM + IN_DIM)
        mask = out + (long)BATCH * OUT_DIM;   // tuple order: (out, mask)

    k_topk<<<1, 1024>>>(logits, mask);

    // PDL launch: k_mlp may start while k_topk drains; it synchronizes via
    // cudaGridDependencySynchronize() before touching g_topk_idx.
    cudaLaunchConfig_t cfg = {};
    cfg.gridDim  = dim3(MLP_GRID);
    cfg.blockDim = dim3(MLP_BLK);
    cfg.dynamicSmemBytes = 0;
    cfg.stream = 0;
    cudaLaunchAttribute attrs[1];
    attrs[0].id = cudaLaunchAttributeProgrammaticStreamSerialization;
    attrs[0].val.programmaticStreamSerializationAllowed = 1;
    cfg.attrs = attrs;
    cfg.numAttrs = 1;
    cudaError_t err = cudaLaunchKernelEx(&cfg, k_mlp, x, W1, b1, W2, b2, W3, b3, out);
    if (err != cudaSuccess) {
        // fallback: plain launch (still correct)
        k_mlp<<<MLP_GRID, MLP_BLK>>>(x, W1, b1, W2, b2, W3, b3, out);
    }
}